// round 7
// baseline (speedup 1.0000x reference)
#include <cuda_runtime.h>
#include <stdint.h>

#define BATCH   4
#define NPTS    100000
#define TOTAL   (BATCH * NPTS)
#define D_IN    16
#define D_TOT   19
#define MLP_N   128
#define GRID_X  468
#define GRID_Y  468
#define VOL     (GRID_X * GRID_Y)
#define NVOX    (BATCH * VOL)          // 876096
#define CAP     16

#define SWEEP_CHUNKS (NVOX / 32)       // 27378 chunks of 32 voxels
// role split: of every 8 blocks, 3 fill + 5 sweep
#define K3_BLOCKS    5472
#define FILL_WARPS   (2052 * 8)        // blocks with bid%8<3  -> 16416 warps
#define SWEEP_WARPS  (3420 * 8)        // remaining            -> 27360 warps

__device__ int d_cnt[NVOX];
__device__ int d_pidx[(size_t)NVOX * CAP];
__device__ int d_occ[NVOX];
__device__ int d_nocc;

// ---- packed f32x2 helpers ----
__device__ __forceinline__ unsigned long long pack2(float lo, float hi) {
    unsigned long long r;
    asm("mov.b64 %0, {%1, %2};" : "=l"(r) : "f"(lo), "f"(hi));
    return r;
}
__device__ __forceinline__ unsigned long long dup2(float v) {
    unsigned long long r;
    asm("mov.b64 %0, {%1, %1};" : "=l"(r) : "f"(v));
    return r;
}
__device__ __forceinline__ unsigned long long fma2(unsigned long long a,
                                                   unsigned long long b,
                                                   unsigned long long c) {
    unsigned long long d;
    asm("fma.rn.f32x2 %0, %1, %2, %3;" : "=l"(d) : "l"(a), "l"(b), "l"(c));
    return d;
}
__device__ __forceinline__ void unpack2(unsigned long long p, float& lo, float& hi) {
    asm("mov.b64 {%0, %1}, %2;" : "=f"(lo), "=f"(hi) : "l"(p));
}

// ---- K1: zero counters + occupied-list head ----
__global__ void zero_cnt_kernel() {
    const int i = blockIdx.x * blockDim.x + threadIdx.x;
    if (i == 0) d_nocc = 0;
    if (i < NVOX / 4) ((int4*)d_cnt)[i] = make_int4(0, 0, 0, 0);
}

// ---- K2: bin valid points; first point appends voxel to occupied list ----
__global__ void __launch_bounds__(256)
bin_points_kernel(const float* __restrict__ xyz,
                  const unsigned int* __restrict__ mask)
{
    const int p = blockIdx.x * blockDim.x + threadIdx.x;
    if (p >= TOTAL) return;
    if (mask[p] == 0u) return;

    const float x = xyz[p * 3 + 0];
    const float y = xyz[p * 3 + 1];
    const float z = xyz[p * 3 + 2];
    const int ivx = (int)floorf(x / 0.32f) + 234;
    const int ivy = (int)floorf(y / 0.32f) + 234;
    const int ivz = (int)floorf(z / 6.0f) + 1;
    if (ivx < 0 || ivx >= GRID_X || ivy < 0 || ivy >= GRID_Y || ivz != 0) return;

    const int batch = p / NPTS;
    const int vid = batch * VOL + ivx * GRID_X + ivy;
    const int slot = atomicAdd(&d_cnt[vid], 1);
    if (slot < CAP) d_pidx[(size_t)vid * CAP + slot] = p;
    if (slot == 0) d_occ[atomicAdd(&d_nocc, 1)] = vid;
}

// ---- fill role: one occupied voxel per warp-iteration, 2-deep pipeline ----
__device__ __forceinline__ void fill_role(int fwarp, int lane,
                                          const float* __restrict__ xyz,
                                          const float* __restrict__ pfeat,
                                          const float* __restrict__ W,
                                          const float* __restrict__ bias,
                                          float* __restrict__ out)
{
    const int n = __ldg(&d_nocc);
    if (fwarp >= n) return;

    // Lane owns output columns 4L..4L+3; W register-resident (amortized ~9 voxels).
    unsigned long long w01[D_TOT], w23[D_TOT];
    #pragma unroll
    for (int d = 0; d < D_TOT; ++d) {
        const float4 wr = __ldg(((const float4*)(W + d * MLP_N)) + lane);
        w01[d] = pack2(wr.x, wr.y);
        w23[d] = pack2(wr.z, wr.w);
    }
    const float4 b4 = __ldg(((const float4*)bias) + lane);
    const unsigned long long b01 = pack2(b4.x, b4.y);
    const unsigned long long b23 = pack2(b4.z, b4.w);

    int idx = fwarp;
    int vid = __ldg(&d_occ[idx]);
    int cnt = __ldg(&d_cnt[vid]);
    int pid = (lane < CAP) ? __ldg(&d_pidx[(size_t)vid * CAP + lane]) : 0;

    while (idx < n) {
        const int idx2 = idx + FILL_WARPS;
        int vid2 = 0, cnt2 = 0, pid2 = 0;
        if (idx2 < n) {                       // prefetch next voxel
            vid2 = __ldg(&d_occ[idx2]);
            cnt2 = __ldg(&d_cnt[vid2]);
            pid2 = (lane < CAP) ? __ldg(&d_pidx[(size_t)vid2 * CAP + lane]) : 0;
        }

        const int npt = cnt < CAP ? cnt : CAP;
        unsigned long long vmax01 = pack2(-1e30f, -1e30f);
        unsigned long long vmax23 = vmax01;

        for (int k = 0; k < npt; ++k) {
            const int p = __shfl_sync(0xffffffffu, pid, k);
            const float x = xyz[p * 3 + 0];
            const float y = xyz[p * 3 + 1];
            const float z = xyz[p * 3 + 2];
            const float dx = x - floorf(x / 0.32f) * 0.32f;
            const float dy = y - floorf(y / 0.32f) * 0.32f;
            const float dz = z - floorf(z / 6.0f) * 6.0f;

            const float4* f4 = (const float4*)(pfeat + (size_t)p * D_IN);
            const float4 fa = f4[0], fb = f4[1], fc = f4[2], fd = f4[3];
            const float vin[D_TOT] = {
                fa.x, fa.y, fa.z, fa.w,
                fb.x, fb.y, fb.z, fb.w,
                fc.x, fc.y, fc.z, fc.w,
                fd.x, fd.y, fd.z, fd.w,
                dx, dy, dz
            };
            unsigned long long acc01 = b01, acc23 = b23;
            #pragma unroll
            for (int d = 0; d < D_TOT; ++d) {
                const unsigned long long vv = dup2(vin[d]);
                acc01 = fma2(vv, w01[d], acc01);
                acc23 = fma2(vv, w23[d], acc23);
            }
            float a0, a1, a2, a3, m0, m1, m2, m3;
            unpack2(acc01, a0, a1); unpack2(acc23, a2, a3);
            unpack2(vmax01, m0, m1); unpack2(vmax23, m2, m3);
            vmax01 = pack2(fmaxf(m0, a0), fmaxf(m1, a1));
            vmax23 = pack2(fmaxf(m2, a2), fmaxf(m3, a3));
        }

        float m0, m1, m2, m3;
        unpack2(vmax01, m0, m1);
        unpack2(vmax23, m2, m3);
        // relu monotone: max-then-relu == max-of-relus
        ((float4*)(out + (size_t)vid * MLP_N))[lane] =
            make_float4(fmaxf(m0, 0.f), fmaxf(m1, 0.f),
                        fmaxf(m2, 0.f), fmaxf(m3, 0.f));

        idx = idx2; vid = vid2; cnt = cnt2; pid = pid2;
    }
}

// ---- sweep role: stream zeros into empty voxels only ----
__device__ __forceinline__ void sweep_role(int swarp, int lane,
                                           float* __restrict__ out)
{
    const float4 z4 = make_float4(0.f, 0.f, 0.f, 0.f);
    for (int cid = swarp; cid < SWEEP_CHUNKS; cid += SWEEP_WARPS) {
        const int vbase = cid * 32;
        const int c = __ldg(&d_cnt[vbase + lane]);
        const unsigned em = __ballot_sync(0xffffffffu, c == 0);  // empty mask
        #pragma unroll 8
        for (int i = 0; i < 32; ++i) {
            if ((em >> i) & 1u) {   // warp-uniform predicate
                __stcs(((float4*)(out + (size_t)(vbase + i) * MLP_N)) + lane, z4);
            }
        }
    }
}

// ---- K3: both roles in one launch; writes disjoint; roles interleaved ----
__global__ void __launch_bounds__(256)
output_kernel(const float* __restrict__ xyz,
              const float* __restrict__ pfeat,
              const float* __restrict__ W,
              const float* __restrict__ bias,
              float* __restrict__ out)
{
    const int lane = threadIdx.x & 31;
    const int widb = threadIdx.x >> 5;              // warp within block (0..7)
    const int grp  = blockIdx.x >> 3;               // group of 8 blocks
    const int sub  = blockIdx.x & 7;

    if (sub < 3) {
        fill_role(grp * 24 + sub * 8 + widb, lane, xyz, pfeat, W, bias, out);
    } else {
        sweep_role(grp * 40 + (sub - 3) * 8 + widb, lane, out);
    }
}

extern "C" void kernel_launch(void* const* d_in, const int* in_sizes, int n_in,
                              void* d_out, int out_size)
{
    const float*        xyz   = (const float*)d_in[0];
    const float*        pfeat = (const float*)d_in[1];
    const unsigned int* mask  = (const unsigned int*)d_in[2];
    const float*        W     = (const float*)d_in[3];
    const float*        bias  = (const float*)d_in[4];
    float*              out   = (float*)d_out;

    zero_cnt_kernel<<<(NVOX / 4 + 511) / 512, 512>>>();
    bin_points_kernel<<<(TOTAL + 255) / 256, 256>>>(xyz, mask);
    output_kernel<<<K3_BLOCKS, 256>>>(xyz, pfeat, W, bias, out);
}

// round 8
// speedup vs baseline: 1.5705x; 1.5705x over previous
#include <cuda_runtime.h>
#include <stdint.h>

#define BATCH   4
#define NPTS    100000
#define TOTAL   (BATCH * NPTS)
#define D_IN    16
#define D_TOT   19
#define MLP_N   128
#define GRID_X  468
#define GRID_Y  468
#define VOL     (GRID_X * GRID_Y)
#define NVOX    (BATCH * VOL)        // 876096 = 27378 * 32
#define CAP     16

#define THREADS 256
#define BLOCKS  740                  // persistent: 5 blocks/SM * 148
#define NWARPS  (BLOCKS * THREADS / 32)

__device__ int d_cnt[NVOX];                 // per-voxel point count
__device__ int d_pidx[(size_t)NVOX * CAP];  // per-voxel point indices

// ---- packed f32x2 helpers (FFMA2, PTX-only) ----
__device__ __forceinline__ unsigned long long dup2(float v) {
    unsigned long long r;
    asm("mov.b64 %0, {%1, %1};" : "=l"(r) : "f"(v));
    return r;
}
__device__ __forceinline__ unsigned long long fma2(unsigned long long a,
                                                   unsigned long long b,
                                                   unsigned long long c) {
    unsigned long long d;
    asm("fma.rn.f32x2 %0, %1, %2, %3;" : "=l"(d) : "l"(a), "l"(b), "l"(c));
    return d;
}
__device__ __forceinline__ void unpack2(unsigned long long p, float& lo, float& hi) {
    asm("mov.b64 {%0, %1}, %2;" : "=f"(lo), "=f"(hi) : "l"(p));
}
__device__ __forceinline__ unsigned long long pack2(float lo, float hi) {
    unsigned long long r;
    asm("mov.b64 %0, {%1, %2};" : "=l"(r) : "f"(lo), "f"(hi));
    return r;
}

// ---- K1: zero counters ----
__global__ void zero_cnt_kernel() {
    const int i = blockIdx.x * blockDim.x + threadIdx.x;
    if (i < NVOX / 4) ((int4*)d_cnt)[i] = make_int4(0, 0, 0, 0);
}

// ---- K2: bin valid points (NO single-address counter — that cost 65us in R6) ----
__global__ void __launch_bounds__(256)
bin_points_kernel(const float* __restrict__ xyz,
                  const unsigned int* __restrict__ mask)
{
    const int p = blockIdx.x * blockDim.x + threadIdx.x;
    if (p >= TOTAL) return;
    if (mask[p] == 0u) return;

    const float x = xyz[p * 3 + 0];
    const float y = xyz[p * 3 + 1];
    const float z = xyz[p * 3 + 2];
    const int ivx = (int)floorf(x / 0.32f) + 234;
    const int ivy = (int)floorf(y / 0.32f) + 234;
    const int ivz = (int)floorf(z / 6.0f) + 1;
    if (ivx < 0 || ivx >= GRID_X || ivy < 0 || ivy >= GRID_Y || ivz != 0) return;

    const int batch = p / NPTS;
    const int vid = batch * VOL + ivx * GRID_X + ivy;
    const int slot = atomicAdd(&d_cnt[vid], 1);
    if (slot < CAP) d_pidx[(size_t)vid * CAP + slot] = p;
}

// ---- K3: fused gather — every voxel written exactly once; W in shared ----
__global__ void __launch_bounds__(THREADS, 5)
gather_kernel(const float* __restrict__ xyz,
              const float* __restrict__ pfeat,
              const float* __restrict__ W,
              const float* __restrict__ bias,
              float* __restrict__ out)
{
    // Shared W: consecutive floats reinterpret directly as f32x2 pairs.
    __shared__ float4 sW4[D_TOT * (MLP_N / 4)];   // 9728 B
    for (int i = threadIdx.x; i < D_TOT * (MLP_N / 4); i += THREADS)
        sW4[i] = ((const float4*)W)[i];
    __syncthreads();

    const int lane  = threadIdx.x & 31;
    const int gwarp = (blockIdx.x * THREADS + threadIdx.x) >> 5;

    // Lane owns output columns 4L..4L+3.
    const float4 b4 = __ldg(((const float4*)bias) + lane);
    const unsigned long long b01 = pack2(b4.x, b4.y);
    const unsigned long long b23 = pack2(b4.z, b4.w);
    const float4 zero4 = make_float4(0.f, 0.f, 0.f, 0.f);

    int chunk = gwarp * 32;
    int c = (chunk < NVOX) ? __ldg(&d_cnt[chunk + lane]) : 0;   // coalesced counts

    for (; chunk < NVOX; chunk += NWARPS * 32) {
        const int nxt = chunk + NWARPS * 32;
        const int cnext = (nxt < NVOX) ? __ldg(&d_cnt[nxt + lane]) : 0;  // prefetch

        #pragma unroll 4
        for (int i = 0; i < 32; ++i) {
            const int ci = __shfl_sync(0xffffffffu, c, i);
            const int v  = chunk + i;
            float4* dst = ((float4*)(out + (size_t)v * MLP_N)) + lane;
            if (ci == 0) {                       // warp-uniform
                __stcs(dst, zero4);              // streaming zero, no L2 pollution
                continue;
            }
            const int npt = ci < CAP ? ci : CAP;
            unsigned long long vmax01 = pack2(-1e30f, -1e30f);
            unsigned long long vmax23 = vmax01;

            for (int k = 0; k < npt; ++k) {
                const int p = __ldg(&d_pidx[(size_t)v * CAP + k]);
                const float x = xyz[p * 3 + 0];
                const float y = xyz[p * 3 + 1];
                const float z = xyz[p * 3 + 2];
                const float dx = x - floorf(x / 0.32f) * 0.32f;
                const float dy = y - floorf(y / 0.32f) * 0.32f;
                const float dz = z - floorf(z / 6.0f) * 6.0f;

                const float4* f4 = (const float4*)(pfeat + (size_t)p * D_IN);
                const float4 fa = f4[0], fb = f4[1], fc = f4[2], fd = f4[3];
                const float vin[D_TOT] = {
                    fa.x, fa.y, fa.z, fa.w,
                    fb.x, fb.y, fb.z, fb.w,
                    fc.x, fc.y, fc.z, fc.w,
                    fd.x, fd.y, fd.z, fd.w,
                    dx, dy, dz
                };
                unsigned long long acc01 = b01, acc23 = b23;
                #pragma unroll
                for (int d = 0; d < D_TOT; ++d) {
                    // LDS.128: two packed f32x2 pairs for this lane's 4 columns
                    const ulonglong2 wp =
                        *(const ulonglong2*)(sW4 + d * (MLP_N / 4) + lane);
                    const unsigned long long vv = dup2(vin[d]);
                    acc01 = fma2(vv, wp.x, acc01);
                    acc23 = fma2(vv, wp.y, acc23);
                }
                float a0, a1, a2, a3, m0, m1, m2, m3;
                unpack2(acc01, a0, a1); unpack2(acc23, a2, a3);
                unpack2(vmax01, m0, m1); unpack2(vmax23, m2, m3);
                vmax01 = pack2(fmaxf(m0, a0), fmaxf(m1, a1));
                vmax23 = pack2(fmaxf(m2, a2), fmaxf(m3, a3));
            }

            float m0, m1, m2, m3;
            unpack2(vmax01, m0, m1);
            unpack2(vmax23, m2, m3);
            // relu monotone: max-then-relu == max-of-relus; empties exact 0
            __stcs(dst, make_float4(fmaxf(m0, 0.f), fmaxf(m1, 0.f),
                                    fmaxf(m2, 0.f), fmaxf(m3, 0.f)));
        }
        c = cnext;
    }
}

extern "C" void kernel_launch(void* const* d_in, const int* in_sizes, int n_in,
                              void* d_out, int out_size)
{
    const float*        xyz   = (const float*)d_in[0];
    const float*        pfeat = (const float*)d_in[1];
    const unsigned int* mask  = (const unsigned int*)d_in[2];
    const float*        W     = (const float*)d_in[3];
    const float*        bias  = (const float*)d_in[4];
    float*              out   = (float*)d_out;

    zero_cnt_kernel<<<(NVOX / 4 + 511) / 512, 512>>>();
    bin_points_kernel<<<(TOTAL + 255) / 256, 256>>>(xyz, mask);
    gather_kernel<<<BLOCKS, THREADS>>>(xyz, pfeat, W, bias, out);
}

// round 9
// speedup vs baseline: 1.6311x; 1.0386x over previous
#include <cuda_runtime.h>
#include <stdint.h>

#define BATCH   4
#define NPTS    100000
#define TOTAL   (BATCH * NPTS)
#define D_IN    16
#define D_TOT   19
#define MLP_N   128
#define GRID_X  468
#define GRID_Y  468
#define VOL     (GRID_X * GRID_Y)
#define NVOX    (BATCH * VOL)        // 876096 = 27378 * 32
#define CAP     16

#define THREADS 256
#define BLOCKS  740                  // persistent: 5 blocks/SM * 148
#define NWARPS  (BLOCKS * THREADS / 32)
#define STRIDE  (NWARPS * 32)

__device__ int d_cnt[NVOX];                 // per-voxel point count (self-zeroing)
__device__ int d_pidx[(size_t)NVOX * CAP];  // per-voxel point indices

// ---- packed f32x2 helpers (FFMA2, PTX-only) ----
__device__ __forceinline__ unsigned long long dup2(float v) {
    unsigned long long r;
    asm("mov.b64 %0, {%1, %1};" : "=l"(r) : "f"(v));
    return r;
}
__device__ __forceinline__ unsigned long long fma2(unsigned long long a,
                                                   unsigned long long b,
                                                   unsigned long long c) {
    unsigned long long d;
    asm("fma.rn.f32x2 %0, %1, %2, %3;" : "=l"(d) : "l"(a), "l"(b), "l"(c));
    return d;
}
__device__ __forceinline__ void unpack2(unsigned long long p, float& lo, float& hi) {
    asm("mov.b64 {%0, %1}, %2;" : "=f"(lo), "=f"(hi) : "l"(p));
}
__device__ __forceinline__ unsigned long long pack2(float lo, float hi) {
    unsigned long long r;
    asm("mov.b64 %0, {%1, %2};" : "=l"(r) : "f"(lo), "f"(hi));
    return r;
}
__device__ __forceinline__ void prefetchL1(const void* ptr) {
    asm volatile("prefetch.global.L1 [%0];" :: "l"(ptr));
}

// ---- K2: bin valid points (no single-address counters!) ----
__global__ void __launch_bounds__(256)
bin_points_kernel(const float* __restrict__ xyz,
                  const unsigned int* __restrict__ mask)
{
    const int p = blockIdx.x * blockDim.x + threadIdx.x;
    if (p >= TOTAL) return;
    if (mask[p] == 0u) return;

    const float x = xyz[p * 3 + 0];
    const float y = xyz[p * 3 + 1];
    const float z = xyz[p * 3 + 2];
    const int ivx = (int)floorf(x / 0.32f) + 234;
    const int ivy = (int)floorf(y / 0.32f) + 234;
    const int ivz = (int)floorf(z / 6.0f) + 1;
    if (ivx < 0 || ivx >= GRID_X || ivy < 0 || ivy >= GRID_Y || ivz != 0) return;

    const int batch = p / NPTS;
    const int vid = batch * VOL + ivx * GRID_X + ivy;
    const int slot = atomicAdd(&d_cnt[vid], 1);
    if (slot < CAP) d_pidx[(size_t)vid * CAP + slot] = p;
}

// ---- K3: fused gather; every voxel written exactly once; self-zeroes d_cnt ----
__global__ void __launch_bounds__(THREADS, 5)
gather_kernel(const float* __restrict__ xyz,
              const float* __restrict__ pfeat,
              const float* __restrict__ W,
              const float* __restrict__ bias,
              float* __restrict__ out)
{
    __shared__ float4 sW4[D_TOT * (MLP_N / 4)];   // 9728 B, rows = packed f32x2 pairs
    for (int i = threadIdx.x; i < D_TOT * (MLP_N / 4); i += THREADS)
        sW4[i] = ((const float4*)W)[i];
    __syncthreads();

    const int lane  = threadIdx.x & 31;
    const int gwarp = (blockIdx.x * THREADS + threadIdx.x) >> 5;

    const float4 b4 = __ldg(((const float4*)bias) + lane);
    const unsigned long long b01 = pack2(b4.x, b4.y);
    const unsigned long long b23 = pack2(b4.z, b4.w);
    const float4 zero4 = make_float4(0.f, 0.f, 0.f, 0.f);

    int chunk = gwarp * 32;

    // Pipeline state: counts 2 chunks deep, first-pidx 1 chunk deep (lane-parallel).
    int c = 0, c1 = 0, p = 0;
    if (chunk < NVOX) {
        c = __ldg(&d_cnt[chunk + lane]);
        p = (c > 0) ? __ldg(&d_pidx[(size_t)(chunk + lane) * CAP]) : 0;
        if (c > 0) {                       // warm L1 for this chunk's first points
            prefetchL1(xyz + (size_t)p * 3);
            prefetchL1(pfeat + (size_t)p * D_IN);
        }
    }
    if (chunk + STRIDE < NVOX) c1 = __ldg(&d_cnt[chunk + STRIDE + lane]);

    for (; chunk < NVOX; chunk += STRIDE) {
        // Issue next-next count load + next first-pidx load (independent of processing).
        const int nxt  = chunk + STRIDE;
        const int nxt2 = chunk + 2 * STRIDE;
        const int c2 = (nxt2 < NVOX) ? __ldg(&d_cnt[nxt2 + lane]) : 0;
        int p1 = 0;
        if (nxt < NVOX && c1 > 0)
            p1 = __ldg(&d_pidx[(size_t)(nxt + lane) * CAP]);

        d_cnt[chunk + lane] = 0;          // reset for the next replay (exclusive owner)

        #pragma unroll 4
        for (int i = 0; i < 32; ++i) {
            const int ci = __shfl_sync(0xffffffffu, c, i);
            const int v  = chunk + i;
            float4* dst = ((float4*)(out + (size_t)v * MLP_N)) + lane;
            if (ci == 0) {                       // warp-uniform
                __stcs(dst, zero4);
                continue;
            }
            const int npt = ci < CAP ? ci : CAP;
            unsigned long long vmax01 = pack2(-1e30f, -1e30f);
            unsigned long long vmax23 = vmax01;

            for (int k = 0; k < npt; ++k) {
                // k==0: index was lane-parallel-prefetched; data L1-warm.
                const int pt = (k == 0) ? __shfl_sync(0xffffffffu, p, i)
                                        : __ldg(&d_pidx[(size_t)v * CAP + k]);
                const float x = xyz[pt * 3 + 0];
                const float y = xyz[pt * 3 + 1];
                const float z = xyz[pt * 3 + 2];
                const float dx = x - floorf(x / 0.32f) * 0.32f;
                const float dy = y - floorf(y / 0.32f) * 0.32f;
                const float dz = z - floorf(z / 6.0f) * 6.0f;

                const float4* f4 = (const float4*)(pfeat + (size_t)pt * D_IN);
                const float4 fa = f4[0], fb = f4[1], fc = f4[2], fd = f4[3];
                const float vin[D_TOT] = {
                    fa.x, fa.y, fa.z, fa.w,
                    fb.x, fb.y, fb.z, fb.w,
                    fc.x, fc.y, fc.z, fc.w,
                    fd.x, fd.y, fd.z, fd.w,
                    dx, dy, dz
                };
                unsigned long long acc01 = b01, acc23 = b23;
                #pragma unroll
                for (int d = 0; d < D_TOT; ++d) {
                    const ulonglong2 wp =
                        *(const ulonglong2*)(sW4 + d * (MLP_N / 4) + lane);
                    const unsigned long long vv = dup2(vin[d]);
                    acc01 = fma2(vv, wp.x, acc01);
                    acc23 = fma2(vv, wp.y, acc23);
                }
                float a0, a1, a2, a3, m0, m1, m2, m3;
                unpack2(acc01, a0, a1); unpack2(acc23, a2, a3);
                unpack2(vmax01, m0, m1); unpack2(vmax23, m2, m3);
                vmax01 = pack2(fmaxf(m0, a0), fmaxf(m1, a1));
                vmax23 = pack2(fmaxf(m2, a2), fmaxf(m3, a3));
            }

            float m0, m1, m2, m3;
            unpack2(vmax01, m0, m1);
            unpack2(vmax23, m2, m3);
            // relu monotone: max-then-relu == max-of-relus
            __stcs(dst, make_float4(fmaxf(m0, 0.f), fmaxf(m1, 0.f),
                                    fmaxf(m2, 0.f), fmaxf(m3, 0.f)));
        }

        // p1 has landed by now (issued ~700 cyc ago): warm L1 for next chunk.
        if (c1 > 0) {
            prefetchL1(xyz + (size_t)p1 * 3);
            prefetchL1(pfeat + (size_t)p1 * D_IN);
        }
        c = c1; c1 = c2; p = p1;
    }
}

extern "C" void kernel_launch(void* const* d_in, const int* in_sizes, int n_in,
                              void* d_out, int out_size)
{
    const float*        xyz   = (const float*)d_in[0];
    const float*        pfeat = (const float*)d_in[1];
    const unsigned int* mask  = (const unsigned int*)d_in[2];
    const float*        W     = (const float*)d_in[3];
    const float*        bias  = (const float*)d_in[4];
    float*              out   = (float*)d_out;

    // d_cnt starts zeroed (static init) and is re-zeroed by gather_kernel each call.
    bin_points_kernel<<<(TOTAL + 255) / 256, 256>>>(xyz, mask);
    gather_kernel<<<BLOCKS, THREADS>>>(xyz, pfeat, W, bias, out);
}